// round 7
// baseline (speedup 1.0000x reference)
#include <cuda_runtime.h>
#include <cstdint>

// ============================================================================
// Quantized linear layer (distiller RangeLinearQuantParamLayerWrapper)
//   x[4096,4096] f32, W[4096,4096] f32 ([out,in]), b[4096] f32 -> out[4096,4096] f32
//
// Target is base sm_100 (no tcgen05/TMEM). int8 mma.sync m16n8k32 s8*s8+s32
// (exact integer math == reference semantics) + cp.async 4-stage pipeline
// + ldmatrix.x4 fragment loads. Block tile 128x256, warp tile 64x64.
// ============================================================================

#define DIM 4096
#define NELEM (DIM * DIM)

// ---------------- scratch (device globals; no runtime allocation) -----------
__device__ __align__(16) signed char g_xq8[NELEM];   // 16 MB
__device__ __align__(16) signed char g_wq8[NELEM];   // 16 MB
__device__ float         g_accum[NELEM];             // 64 MB
__device__ float         g_bq[DIM];
__device__ unsigned      g_umax[4];                  // max|x|,max|W|,(unused),max|accum|

// ============================================================================
// small kernels (scales recomputed inline from g_umax -> fewer launches)
// ============================================================================
__global__ void k_init() {
    if (threadIdx.x < 4) g_umax[threadIdx.x] = 0u;
}

__device__ __forceinline__ void maxabs_body(const float4* __restrict__ p, int n4,
                                            int slot, int bi, int nblk) {
    float m = 0.f;
    for (int i = bi * blockDim.x + threadIdx.x; i < n4; i += nblk * blockDim.x) {
        float4 v = p[i];
        m = fmaxf(m, fmaxf(fmaxf(fabsf(v.x), fabsf(v.y)), fmaxf(fabsf(v.z), fabsf(v.w))));
    }
    #pragma unroll
    for (int o = 16; o; o >>= 1) m = fmaxf(m, __shfl_xor_sync(0xFFFFFFFFu, m, o));
    __shared__ float sm[32];
    int w = threadIdx.x >> 5, l = threadIdx.x & 31;
    if (l == 0) sm[w] = m;
    __syncthreads();
    if (w == 0) {
        m = (l < (int)(blockDim.x >> 5)) ? sm[l] : 0.f;
        #pragma unroll
        for (int o = 16; o; o >>= 1) m = fmaxf(m, __shfl_xor_sync(0xFFFFFFFFu, m, o));
        if (l == 0) atomicMax(&g_umax[slot], __float_as_uint(m));
    }
}

// one launch: first half of blocks reduce x, second half reduce W
__global__ void k_maxabs2(const float4* __restrict__ x, const float4* __restrict__ W) {
    int nb = gridDim.x >> 1;
    if ((int)blockIdx.x < nb) maxabs_body(x, NELEM / 4, 0, blockIdx.x, nb);
    else                      maxabs_body(W, NELEM / 4, 1, blockIdx.x - nb, nb);
}

// quantize x and W -> s8; block 0 additionally handles the bias path
// (max|b| block-locally, then bq) -- b is only 16 KB.
__global__ void k_quant8(const float4* __restrict__ x, const float4* __restrict__ W,
                         const float* __restrict__ b) {
    float sx = 255.0f / (2.0f * __uint_as_float(g_umax[0]));
    float sw = 255.0f / (2.0f * __uint_as_float(g_umax[1]));

    if (blockIdx.x == 0) {
        // ---- bias: block-local max|b|, then bq = rint(clamp(rint(b*b_s)) * acc_s/b_s)
        __shared__ float s_mb;
        float m = 0.f;
        for (int i = threadIdx.x; i < DIM; i += blockDim.x) m = fmaxf(m, fabsf(b[i]));
        #pragma unroll
        for (int o = 16; o; o >>= 1) m = fmaxf(m, __shfl_xor_sync(0xFFFFFFFFu, m, o));
        __shared__ float sm[32];
        int w = threadIdx.x >> 5, l = threadIdx.x & 31;
        if (l == 0) sm[w] = m;
        __syncthreads();
        if (w == 0) {
            m = (l < (int)(blockDim.x >> 5)) ? sm[l] : 0.f;
            #pragma unroll
            for (int o = 16; o; o >>= 1) m = fmaxf(m, __shfl_xor_sync(0xFFFFFFFFu, m, o));
            if (l == 0) s_mb = m;
        }
        __syncthreads();
        float b_s = 255.0f / (2.0f * s_mb);
        float rb  = (sx * sw) / b_s;
        for (int i = threadIdx.x; i < DIM; i += blockDim.x) {
            float base = fminf(127.f, fmaxf(-128.f, rintf(b[i] * b_s)));
            g_bq[i] = rintf(base * rb);  // |val| << 2^31 -> accum-range clip is a no-op
        }
    }

    const int n16 = NELEM / 16;
    for (int i = blockIdx.x * blockDim.x + threadIdx.x; i < 2 * n16; i += gridDim.x * blockDim.x) {
        int which = i >= n16;
        int idx = which ? i - n16 : i;
        const float4* src = which ? W : x;
        float s = which ? sw : sx;
        int4* dst = reinterpret_cast<int4*>(which ? g_wq8 : g_xq8);
        int p[4];
        #pragma unroll
        for (int j = 0; j < 4; j++) {
            float4 v = src[idx * 4 + j];
            int q0 = max(-128, min(127, __float2int_rn(v.x * s)));
            int q1 = max(-128, min(127, __float2int_rn(v.y * s)));
            int q2 = max(-128, min(127, __float2int_rn(v.z * s)));
            int q3 = max(-128, min(127, __float2int_rn(v.w * s)));
            p[j] = (q0 & 0xFF) | ((q1 & 0xFF) << 8) | ((q2 & 0xFF) << 16) | ((q3 & 0xFF) << 24);
        }
        dst[idx] = make_int4(p[0], p[1], p[2], p[3]);
    }
}

__global__ void k_requant(float4* __restrict__ out, int n4) {
    float in_s   = 255.0f / (2.0f * __uint_as_float(g_umax[0]));
    float w_s    = 255.0f / (2.0f * __uint_as_float(g_umax[1]));
    float acc_s  = in_s * w_s;
    float out_sat = __uint_as_float(g_umax[3]) / acc_s;
    float out_s  = 255.0f / (2.0f * out_sat);
    float ratio  = out_s / acc_s;
    const float4* acc = reinterpret_cast<const float4*>(g_accum);
    for (int i = blockIdx.x * blockDim.x + threadIdx.x; i < n4; i += gridDim.x * blockDim.x) {
        float4 v = acc[i];
        float4 o;
        o.x = fminf(127.f, fmaxf(-128.f, rintf(v.x * ratio))) / out_s;
        o.y = fminf(127.f, fmaxf(-128.f, rintf(v.y * ratio))) / out_s;
        o.z = fminf(127.f, fmaxf(-128.f, rintf(v.z * ratio))) / out_s;
        o.w = fminf(127.f, fmaxf(-128.f, rintf(v.w * ratio))) / out_s;
        out[i] = o;
    }
}

// ============================================================================
// int8 GEMM: accum[m,n] = sum_k xq[m,k]*wq[n,k] + bq[n]; plus global max|accum|
//   block 128x256, BK=64, 8 warps (warp tile 64x64), 4-stage cp.async pipeline
//   ldmatrix.x4 fragment loads, mma.sync.m16n8k32.s8.s8.s32
// ============================================================================
#define BM 128
#define BN 256
#define BK 64
#define NSTAGE 4
#define KSTAGES (DIM / BK)     // 64
#define ROWPAD 80              // 64B rows padded to 80B: 8-row ldmatrix banks distinct
#define A_STAGE_BYTES (BM * ROWPAD)                   // 10240
#define B_STAGE_BYTES (BN * ROWPAD)                   // 20480
#define GEMM_SMEM_BYTES (NSTAGE * (A_STAGE_BYTES + B_STAGE_BYTES))  // 122880

__device__ __forceinline__ uint32_t smem_u32(const void* p) {
    uint32_t a;
    asm("{ .reg .u64 t; cvta.to.shared.u64 t, %1; cvt.u32.u64 %0, t; }" : "=r"(a) : "l"(p));
    return a;
}

__device__ __forceinline__ void cpasync16(uint32_t dst, const void* src) {
    asm volatile("cp.async.cg.shared.global [%0], [%1], 16;" :: "r"(dst), "l"(src) : "memory");
}
#define CP_COMMIT() asm volatile("cp.async.commit_group;" ::: "memory")
#define CP_WAIT2()  asm volatile("cp.async.wait_group 2;" ::: "memory")

__device__ __forceinline__ void ldsm4(unsigned& r0, unsigned& r1, unsigned& r2, unsigned& r3,
                                      uint32_t addr) {
    asm volatile("ldmatrix.sync.aligned.m8n8.x4.shared.b16 {%0,%1,%2,%3}, [%4];"
                 : "=r"(r0), "=r"(r1), "=r"(r2), "=r"(r3) : "r"(addr));
}

__device__ __forceinline__ void mma_s8(int* d, const unsigned* a, const unsigned* b) {
    asm volatile(
        "mma.sync.aligned.m16n8k32.row.col.s32.s8.s8.s32 "
        "{%0,%1,%2,%3}, {%4,%5,%6,%7}, {%8,%9}, {%0,%1,%2,%3};"
        : "+r"(d[0]), "+r"(d[1]), "+r"(d[2]), "+r"(d[3])
        : "r"(a[0]), "r"(a[1]), "r"(a[2]), "r"(a[3]), "r"(b[0]), "r"(b[1]));
}

__device__ __forceinline__ void load_stage(uint32_t sA, uint32_t sB, int s,
                                           const signed char* Ag, const signed char* Bg,
                                           int tid) {
    int k0 = s * BK;
    // A: 128 rows x 4 16B-chunks = 512 chunks
    #pragma unroll
    for (int i = 0; i < 2; i++) {
        int chunk = tid + i * 256;
        int r = chunk >> 2, c = chunk & 3;
        cpasync16(sA + (uint32_t)(r * ROWPAD + c * 16), Ag + (size_t)r * DIM + k0 + c * 16);
    }
    // B: 256 rows x 4 chunks = 1024 chunks
    #pragma unroll
    for (int i = 0; i < 4; i++) {
        int chunk = tid + i * 256;
        int r = chunk >> 2, c = chunk & 3;
        cpasync16(sB + (uint32_t)(r * ROWPAD + c * 16), Bg + (size_t)r * DIM + k0 + c * 16);
    }
    CP_COMMIT();
}

__global__ void __launch_bounds__(256) k_gemm() {
    extern __shared__ char dsm[];
    __shared__ float s_bq[BN];

    const int tid  = threadIdx.x;
    const int wid  = tid >> 5;
    const int lane = tid & 31;
    const int m0 = blockIdx.y * BM;
    const int n0 = blockIdx.x * BN;
    const int warp_m = (wid >> 2) * 64;   // 0 or 64
    const int warp_n = (wid & 3) * 64;    // 0,64,128,192

    uint32_t sA0 = smem_u32(dsm);
    uint32_t sB0 = sA0 + NSTAGE * A_STAGE_BYTES;

    s_bq[tid] = g_bq[n0 + tid];           // 256 threads cover BN=256

    const signed char* Ag = g_xq8 + (size_t)m0 * DIM;
    const signed char* Bg = g_wq8 + (size_t)n0 * DIM;

    int acc[4][8][4];
    #pragma unroll
    for (int im = 0; im < 4; im++)
        #pragma unroll
        for (int in = 0; in < 8; in++)
            #pragma unroll
            for (int j = 0; j < 4; j++) acc[im][in][j] = 0;

    load_stage(sA0, sB0, 0, Ag, Bg, tid);
    load_stage(sA0 + A_STAGE_BYTES, sB0 + B_STAGE_BYTES, 1, Ag, Bg, tid);
    load_stage(sA0 + 2 * A_STAGE_BYTES, sB0 + 2 * B_STAGE_BYTES, 2, Ag, Bg, tid);

    // ldmatrix per-thread address components (same mapping validated in R3/R5)
    const uint32_t a_off = (uint32_t)((lane & 15) * ROWPAD + ((lane >> 4) << 4));
    const uint32_t b_off = (uint32_t)((((lane & 7) + ((lane >> 4) << 3)) * ROWPAD) + (((lane >> 3) & 1) << 4));

    for (int s = 0; s < KSTAGES; s++) {
        int buf = s % NSTAGE;
        CP_WAIT2();
        __syncthreads();

        if (s + 3 < KSTAGES) {
            int nb = (s + 3) % NSTAGE;
            load_stage(sA0 + nb * A_STAGE_BYTES, sB0 + nb * B_STAGE_BYTES, s + 3, Ag, Bg, tid);
        } else {
            CP_COMMIT();
        }

        uint32_t aBase = sA0 + buf * A_STAGE_BYTES + (uint32_t)(warp_m * ROWPAD) + a_off;
        uint32_t bBase = sB0 + buf * B_STAGE_BYTES + (uint32_t)(warp_n * ROWPAD) + b_off;

        #pragma unroll
        for (int kstep = 0; kstep < 2; kstep++) {
            uint32_t kb = (uint32_t)(kstep * 32);
            unsigned afrag[4][4];
            #pragma unroll
            for (int im = 0; im < 4; im++)
                ldsm4(afrag[im][0], afrag[im][1], afrag[im][2], afrag[im][3],
                      aBase + (uint32_t)(im * 16 * ROWPAD) + kb);
            unsigned bfrag[8][2];
            #pragma unroll
            for (int p = 0; p < 4; p++)
                ldsm4(bfrag[2 * p][0], bfrag[2 * p][1], bfrag[2 * p + 1][0], bfrag[2 * p + 1][1],
                      bBase + (uint32_t)(p * 16 * ROWPAD) + kb);
            #pragma unroll
            for (int im = 0; im < 4; im++)
                #pragma unroll
                for (int in = 0; in < 8; in++)
                    mma_s8(acc[im][in], afrag[im], bfrag[in]);
        }
    }

    // -------- epilogue: + bq, write f32 accum, global max|accum| --------
    __syncthreads();
    const int r = lane >> 2;
    const int c = lane & 3;
    float lmax = 0.f;
    #pragma unroll
    for (int im = 0; im < 4; im++) {
        int r0 = m0 + warp_m + im * 16 + r;
        #pragma unroll
        for (int in = 0; in < 8; in++) {
            int cl = warp_n + in * 8 + c * 2;
            float b0 = s_bq[cl], b1 = s_bq[cl + 1];
            float v0 = (float)acc[im][in][0] + b0;
            float v1 = (float)acc[im][in][1] + b1;
            float v2 = (float)acc[im][in][2] + b0;
            float v3 = (float)acc[im][in][3] + b1;
            lmax = fmaxf(lmax, fmaxf(fmaxf(fabsf(v0), fabsf(v1)), fmaxf(fabsf(v2), fabsf(v3))));
            float2* p0 = reinterpret_cast<float2*>(g_accum + (size_t)r0 * DIM + n0 + cl);
            float2* p1 = reinterpret_cast<float2*>(g_accum + (size_t)(r0 + 8) * DIM + n0 + cl);
            *p0 = make_float2(v0, v1);
            *p1 = make_float2(v2, v3);
        }
    }
    #pragma unroll
    for (int o = 16; o; o >>= 1) lmax = fmaxf(lmax, __shfl_xor_sync(0xFFFFFFFFu, lmax, o));
    if (lane == 0) atomicMax(&g_umax[3], __float_as_uint(lmax));
}

// ============================================================================
// kernel_launch
// ============================================================================
extern "C" void kernel_launch(void* const* d_in, const int* in_sizes, int n_in,
                              void* d_out, int out_size) {
    const float* x = (const float*)d_in[0];
    const float* W = (const float*)d_in[1];
    const float* b = (const float*)d_in[2];

    cudaFuncSetAttribute(k_gemm, cudaFuncAttributeMaxDynamicSharedMemorySize, GEMM_SMEM_BYTES);

    k_init<<<1, 32>>>();
    k_maxabs2<<<2048, 256>>>((const float4*)x, (const float4*)W);
    k_quant8<<<2048, 256>>>((const float4*)x, (const float4*)W, b);

    dim3 grid(DIM / BN, DIM / BM);
    k_gemm<<<grid, 256, GEMM_SMEM_BYTES>>>();

    k_requant<<<2048, 256>>>((float4*)d_out, NELEM / 4);
}

// round 8
// speedup vs baseline: 1.0598x; 1.0598x over previous
#include <cuda_runtime.h>
#include <cstdint>

// ============================================================================
// Quantized linear layer (distiller RangeLinearQuantParamLayerWrapper)
//   x[4096,4096] f32, W[4096,4096] f32 ([out,in]), b[4096] f32 -> out[4096,4096] f32
//
// Target is base sm_100 (no tcgen05/TMEM). int8 mma.sync m16n8k32 s8*s8+s32
// (exact integer math == reference semantics).
// GEMM: block 128x256, BK=128, 512 threads (16 warps, warp tile 64x32),
// 3-stage cp.async pipeline, ldmatrix.x4 fragment loads.
// Calibrated: legacy IMMA peak ~2048 MACs/cyc/SM -> floor ~126us; R6 bound by
// occupancy (8 warps/SM). This config: 16 warps/SM + 2x longer compute runs.
// ============================================================================

#define DIM 4096
#define NELEM (DIM * DIM)

// ---------------- scratch (device globals; no runtime allocation) -----------
__device__ __align__(16) signed char g_xq8[NELEM];   // 16 MB
__device__ __align__(16) signed char g_wq8[NELEM];   // 16 MB
__device__ float         g_accum[NELEM];             // 64 MB
__device__ float         g_bq[DIM];
__device__ unsigned      g_umax[4];                  // max|x|,max|W|,(unused),max|accum|

// ============================================================================
// small kernels (scales recomputed inline from g_umax -> fewer launches)
// ============================================================================
__global__ void k_init() {
    if (threadIdx.x < 4) g_umax[threadIdx.x] = 0u;
}

__device__ __forceinline__ void maxabs_body(const float4* __restrict__ p, int n4,
                                            int slot, int bi, int nblk) {
    float m = 0.f;
    for (int i = bi * blockDim.x + threadIdx.x; i < n4; i += nblk * blockDim.x) {
        float4 v = p[i];
        m = fmaxf(m, fmaxf(fmaxf(fabsf(v.x), fabsf(v.y)), fmaxf(fabsf(v.z), fabsf(v.w))));
    }
    #pragma unroll
    for (int o = 16; o; o >>= 1) m = fmaxf(m, __shfl_xor_sync(0xFFFFFFFFu, m, o));
    __shared__ float sm[32];
    int w = threadIdx.x >> 5, l = threadIdx.x & 31;
    if (l == 0) sm[w] = m;
    __syncthreads();
    if (w == 0) {
        m = (l < (int)(blockDim.x >> 5)) ? sm[l] : 0.f;
        #pragma unroll
        for (int o = 16; o; o >>= 1) m = fmaxf(m, __shfl_xor_sync(0xFFFFFFFFu, m, o));
        if (l == 0) atomicMax(&g_umax[slot], __float_as_uint(m));
    }
}

__global__ void k_maxabs2(const float4* __restrict__ x, const float4* __restrict__ W) {
    int nb = gridDim.x >> 1;
    if ((int)blockIdx.x < nb) maxabs_body(x, NELEM / 4, 0, blockIdx.x, nb);
    else                      maxabs_body(W, NELEM / 4, 1, blockIdx.x - nb, nb);
}

// quantize x and W -> s8; block 0 additionally handles the bias path
__global__ void k_quant8(const float4* __restrict__ x, const float4* __restrict__ W,
                         const float* __restrict__ b) {
    float sx = 255.0f / (2.0f * __uint_as_float(g_umax[0]));
    float sw = 255.0f / (2.0f * __uint_as_float(g_umax[1]));

    if (blockIdx.x == 0) {
        __shared__ float s_mb;
        float m = 0.f;
        for (int i = threadIdx.x; i < DIM; i += blockDim.x) m = fmaxf(m, fabsf(b[i]));
        #pragma unroll
        for (int o = 16; o; o >>= 1) m = fmaxf(m, __shfl_xor_sync(0xFFFFFFFFu, m, o));
        __shared__ float sm[32];
        int w = threadIdx.x >> 5, l = threadIdx.x & 31;
        if (l == 0) sm[w] = m;
        __syncthreads();
        if (w == 0) {
            m = (l < (int)(blockDim.x >> 5)) ? sm[l] : 0.f;
            #pragma unroll
            for (int o = 16; o; o >>= 1) m = fmaxf(m, __shfl_xor_sync(0xFFFFFFFFu, m, o));
            if (l == 0) s_mb = m;
        }
        __syncthreads();
        float b_s = 255.0f / (2.0f * s_mb);
        float rb  = (sx * sw) / b_s;
        for (int i = threadIdx.x; i < DIM; i += blockDim.x) {
            float base = fminf(127.f, fmaxf(-128.f, rintf(b[i] * b_s)));
            g_bq[i] = rintf(base * rb);  // |val| << 2^31 -> accum-range clip is a no-op
        }
    }

    const int n16 = NELEM / 16;
    for (int i = blockIdx.x * blockDim.x + threadIdx.x; i < 2 * n16; i += gridDim.x * blockDim.x) {
        int which = i >= n16;
        int idx = which ? i - n16 : i;
        const float4* src = which ? W : x;
        float s = which ? sw : sx;
        int4* dst = reinterpret_cast<int4*>(which ? g_wq8 : g_xq8);
        int p[4];
        #pragma unroll
        for (int j = 0; j < 4; j++) {
            float4 v = src[idx * 4 + j];
            int q0 = max(-128, min(127, __float2int_rn(v.x * s)));
            int q1 = max(-128, min(127, __float2int_rn(v.y * s)));
            int q2 = max(-128, min(127, __float2int_rn(v.z * s)));
            int q3 = max(-128, min(127, __float2int_rn(v.w * s)));
            p[j] = (q0 & 0xFF) | ((q1 & 0xFF) << 8) | ((q2 & 0xFF) << 16) | ((q3 & 0xFF) << 24);
        }
        dst[idx] = make_int4(p[0], p[1], p[2], p[3]);
    }
}

__global__ void k_requant(float4* __restrict__ out, int n4) {
    float in_s   = 255.0f / (2.0f * __uint_as_float(g_umax[0]));
    float w_s    = 255.0f / (2.0f * __uint_as_float(g_umax[1]));
    float acc_s  = in_s * w_s;
    float out_sat = __uint_as_float(g_umax[3]) / acc_s;
    float out_s  = 255.0f / (2.0f * out_sat);
    float ratio  = out_s / acc_s;
    const float4* acc = reinterpret_cast<const float4*>(g_accum);
    for (int i = blockIdx.x * blockDim.x + threadIdx.x; i < n4; i += gridDim.x * blockDim.x) {
        float4 v = acc[i];
        float4 o;
        o.x = fminf(127.f, fmaxf(-128.f, rintf(v.x * ratio))) / out_s;
        o.y = fminf(127.f, fmaxf(-128.f, rintf(v.y * ratio))) / out_s;
        o.z = fminf(127.f, fmaxf(-128.f, rintf(v.z * ratio))) / out_s;
        o.w = fminf(127.f, fmaxf(-128.f, rintf(v.w * ratio))) / out_s;
        out[i] = o;
    }
}

// ============================================================================
// int8 GEMM: accum[m,n] = sum_k xq[m,k]*wq[n,k] + bq[n]; plus global max|accum|
//   block 128x256, BK=128, 512 threads / 16 warps (warp tile 64x32),
//   3-stage cp.async pipeline, ldmatrix.x4, mma.sync.m16n8k32.s8.s8.s32
// ============================================================================
#define BM 128
#define BN 256
#define BK 128
#define NSTAGE 3
#define KSTAGES (DIM / BK)     // 32
#define ROWPAD 144             // 128B rows padded to 144B: 8-row ldmatrix banks distinct
#define A_STAGE_BYTES (BM * ROWPAD)                   // 18432
#define B_STAGE_BYTES (BN * ROWPAD)                   // 36864
#define GEMM_SMEM_BYTES (NSTAGE * (A_STAGE_BYTES + B_STAGE_BYTES))  // 165888
#define NTHREADS 512

__device__ __forceinline__ uint32_t smem_u32(const void* p) {
    uint32_t a;
    asm("{ .reg .u64 t; cvta.to.shared.u64 t, %1; cvt.u32.u64 %0, t; }" : "=r"(a) : "l"(p));
    return a;
}

__device__ __forceinline__ void cpasync16(uint32_t dst, const void* src) {
    asm volatile("cp.async.cg.shared.global [%0], [%1], 16;" :: "r"(dst), "l"(src) : "memory");
}
#define CP_COMMIT() asm volatile("cp.async.commit_group;" ::: "memory")
#define CP_WAIT1()  asm volatile("cp.async.wait_group 1;" ::: "memory")

__device__ __forceinline__ void ldsm4(unsigned& r0, unsigned& r1, unsigned& r2, unsigned& r3,
                                      uint32_t addr) {
    asm volatile("ldmatrix.sync.aligned.m8n8.x4.shared.b16 {%0,%1,%2,%3}, [%4];"
                 : "=r"(r0), "=r"(r1), "=r"(r2), "=r"(r3) : "r"(addr));
}

__device__ __forceinline__ void mma_s8(int* d, const unsigned* a, const unsigned* b) {
    asm volatile(
        "mma.sync.aligned.m16n8k32.row.col.s32.s8.s8.s32 "
        "{%0,%1,%2,%3}, {%4,%5,%6,%7}, {%8,%9}, {%0,%1,%2,%3};"
        : "+r"(d[0]), "+r"(d[1]), "+r"(d[2]), "+r"(d[3])
        : "r"(a[0]), "r"(a[1]), "r"(a[2]), "r"(a[3]), "r"(b[0]), "r"(b[1]));
}

__device__ __forceinline__ void load_stage(uint32_t sA, uint32_t sB, int s,
                                           const signed char* Ag, const signed char* Bg,
                                           int tid) {
    int k0 = s * BK;
    // A: 128 rows x 8 16B-chunks = 1024 chunks
    #pragma unroll
    for (int i = 0; i < 2; i++) {
        int chunk = tid + i * NTHREADS;
        int r = chunk >> 3, c = chunk & 7;
        cpasync16(sA + (uint32_t)(r * ROWPAD + c * 16), Ag + (size_t)r * DIM + k0 + c * 16);
    }
    // B: 256 rows x 8 chunks = 2048 chunks
    #pragma unroll
    for (int i = 0; i < 4; i++) {
        int chunk = tid + i * NTHREADS;
        int r = chunk >> 3, c = chunk & 7;
        cpasync16(sB + (uint32_t)(r * ROWPAD + c * 16), Bg + (size_t)r * DIM + k0 + c * 16);
    }
    CP_COMMIT();
}

__global__ void __launch_bounds__(NTHREADS, 1) k_gemm() {
    extern __shared__ char dsm[];
    __shared__ float s_bq[BN];

    const int tid  = threadIdx.x;
    const int wid  = tid >> 5;
    const int lane = tid & 31;
    const int m0 = blockIdx.y * BM;
    const int n0 = blockIdx.x * BN;
    const int warp_m = (wid >> 3) * 64;   // 0 or 64
    const int warp_n = (wid & 7) * 32;    // 0..224

    uint32_t sA0 = smem_u32(dsm);
    uint32_t sB0 = sA0 + NSTAGE * A_STAGE_BYTES;

    if (tid < BN) s_bq[tid] = g_bq[n0 + tid];

    const signed char* Ag = g_xq8 + (size_t)m0 * DIM;
    const signed char* Bg = g_wq8 + (size_t)n0 * DIM;

    int acc[4][4][4];
    #pragma unroll
    for (int im = 0; im < 4; im++)
        #pragma unroll
        for (int in = 0; in < 4; in++)
            #pragma unroll
            for (int j = 0; j < 4; j++) acc[im][in][j] = 0;

    load_stage(sA0, sB0, 0, Ag, Bg, tid);
    load_stage(sA0 + A_STAGE_BYTES, sB0 + B_STAGE_BYTES, 1, Ag, Bg, tid);

    // ldmatrix per-thread address components (mapping validated R3/R5/R7)
    const uint32_t a_off = (uint32_t)((lane & 15) * ROWPAD + ((lane >> 4) << 4));
    const uint32_t b_off = (uint32_t)((((lane & 7) + ((lane >> 4) << 3)) * ROWPAD) + (((lane >> 3) & 1) << 4));

    for (int s = 0; s < KSTAGES; s++) {
        int buf = s % NSTAGE;
        CP_WAIT1();
        __syncthreads();

        // prefetch stage s+2 into buffer (s+2)%3 (consumed at iter s-1)
        if (s + 2 < KSTAGES) {
            int nb = (s + 2) % NSTAGE;
            load_stage(sA0 + nb * A_STAGE_BYTES, sB0 + nb * B_STAGE_BYTES, s + 2, Ag, Bg, tid);
        } else {
            CP_COMMIT();
        }

        uint32_t aBase = sA0 + buf * A_STAGE_BYTES + (uint32_t)(warp_m * ROWPAD) + a_off;
        uint32_t bBase = sB0 + buf * B_STAGE_BYTES + (uint32_t)(warp_n * ROWPAD) + b_off;

        #pragma unroll
        for (int kstep = 0; kstep < 4; kstep++) {
            uint32_t kb = (uint32_t)(kstep * 32);
            unsigned afrag[4][4];
            #pragma unroll
            for (int im = 0; im < 4; im++)
                ldsm4(afrag[im][0], afrag[im][1], afrag[im][2], afrag[im][3],
                      aBase + (uint32_t)(im * 16 * ROWPAD) + kb);
            unsigned bfrag[4][2];
            #pragma unroll
            for (int p = 0; p < 2; p++)
                ldsm4(bfrag[2 * p][0], bfrag[2 * p][1], bfrag[2 * p + 1][0], bfrag[2 * p + 1][1],
                      bBase + (uint32_t)(p * 16 * ROWPAD) + kb);
            #pragma unroll
            for (int im = 0; im < 4; im++)
                #pragma unroll
                for (int in = 0; in < 4; in++)
                    mma_s8(acc[im][in], afrag[im], bfrag[in]);
        }
    }

    // -------- epilogue: + bq, write f32 accum, global max|accum| --------
    __syncthreads();
    const int r = lane >> 2;
    const int c = lane & 3;
    float lmax = 0.f;
    #pragma unroll
    for (int im = 0; im < 4; im++) {
        int r0 = m0 + warp_m + im * 16 + r;
        #pragma unroll
        for (int in = 0; in < 4; in++) {
            int cl = warp_n + in * 8 + c * 2;
            float b0 = s_bq[cl], b1 = s_bq[cl + 1];
            float v0 = (float)acc[im][in][0] + b0;
            float v1 = (float)acc[im][in][1] + b1;
            float v2 = (float)acc[im][in][2] + b0;
            float v3 = (float)acc[im][in][3] + b1;
            lmax = fmaxf(lmax, fmaxf(fmaxf(fabsf(v0), fabsf(v1)), fmaxf(fabsf(v2), fabsf(v3))));
            float2* p0 = reinterpret_cast<float2*>(g_accum + (size_t)r0 * DIM + n0 + cl);
            float2* p1 = reinterpret_cast<float2*>(g_accum + (size_t)(r0 + 8) * DIM + n0 + cl);
            *p0 = make_float2(v0, v1);
            *p1 = make_float2(v2, v3);
        }
    }
    #pragma unroll
    for (int o = 16; o; o >>= 1) lmax = fmaxf(lmax, __shfl_xor_sync(0xFFFFFFFFu, lmax, o));
    if (lane == 0) atomicMax(&g_umax[3], __float_as_uint(lmax));
}

// ============================================================================
// kernel_launch
// ============================================================================
extern "C" void kernel_launch(void* const* d_in, const int* in_sizes, int n_in,
                              void* d_out, int out_size) {
    const float* x = (const float*)d_in[0];
    const float* W = (const float*)d_in[1];
    const float* b = (const float*)d_in[2];

    cudaFuncSetAttribute(k_gemm, cudaFuncAttributeMaxDynamicSharedMemorySize, GEMM_SMEM_BYTES);

    k_init<<<1, 32>>>();
    k_maxabs2<<<2048, 256>>>((const float4*)x, (const float4*)W);
    k_quant8<<<2048, 256>>>((const float4*)x, (const float4*)W, b);

    dim3 grid(DIM / BN, DIM / BM);
    k_gemm<<<grid, NTHREADS, GEMM_SMEM_BYTES>>>();

    k_requant<<<2048, 256>>>((float4*)d_out, NELEM / 4);
}

// round 9
// speedup vs baseline: 1.2444x; 1.1741x over previous
#include <cuda_runtime.h>
#include <cstdint>

// ============================================================================
// Quantized linear layer (distiller RangeLinearQuantParamLayerWrapper)
//   x[4096,4096] f32, W[4096,4096] f32 ([out,in]), b[4096] f32 -> out[4096,4096] f32
//
// Target base sm_100 (no tcgen05). int8 mma.sync m16n8k32 s8*s8+s32 (exact).
// Calibrated: mma.sync rt=16cyc/SMSP -> 1024 MACs/cyc/SM ceiling, floor ~218us.
// GEMM: block 128x128, 256 thr (8 warps, warp 64x32), BK=128, 3-stage cp.async,
// __launch_bounds__(256,2) -> 2 CTAs/SM (barrier desync + soft wave tail).
// ============================================================================

#define DIM 4096
#define NELEM (DIM * DIM)

__device__ __align__(16) signed char g_xq8[NELEM];   // 16 MB
__device__ __align__(16) signed char g_wq8[NELEM];   // 16 MB
__device__ float         g_accum[NELEM];             // 64 MB
__device__ float         g_bq[DIM];
__device__ unsigned      g_umax[4];                  // max|x|,max|W|,(unused),max|accum|

// ============================================================================
// small kernels
// ============================================================================
__global__ void k_init() {
    if (threadIdx.x < 4) g_umax[threadIdx.x] = 0u;
}

__device__ __forceinline__ void maxabs_body(const float4* __restrict__ p, int n4,
                                            int slot, int bi, int nblk) {
    float m = 0.f;
    for (int i = bi * blockDim.x + threadIdx.x; i < n4; i += nblk * blockDim.x) {
        float4 v = p[i];
        m = fmaxf(m, fmaxf(fmaxf(fabsf(v.x), fabsf(v.y)), fmaxf(fabsf(v.z), fabsf(v.w))));
    }
    #pragma unroll
    for (int o = 16; o; o >>= 1) m = fmaxf(m, __shfl_xor_sync(0xFFFFFFFFu, m, o));
    __shared__ float sm[32];
    int w = threadIdx.x >> 5, l = threadIdx.x & 31;
    if (l == 0) sm[w] = m;
    __syncthreads();
    if (w == 0) {
        m = (l < (int)(blockDim.x >> 5)) ? sm[l] : 0.f;
        #pragma unroll
        for (int o = 16; o; o >>= 1) m = fmaxf(m, __shfl_xor_sync(0xFFFFFFFFu, m, o));
        if (l == 0) atomicMax(&g_umax[slot], __float_as_uint(m));
    }
}

__global__ void k_maxabs2(const float4* __restrict__ x, const float4* __restrict__ W) {
    int nb = gridDim.x >> 1;
    if ((int)blockIdx.x < nb) maxabs_body(x, NELEM / 4, 0, blockIdx.x, nb);
    else                      maxabs_body(W, NELEM / 4, 1, blockIdx.x - nb, nb);
}

// quantize x and W -> s8; block 0 additionally handles the bias path
__global__ void k_quant8(const float4* __restrict__ x, const float4* __restrict__ W,
                         const float* __restrict__ b) {
    float sx = 255.0f / (2.0f * __uint_as_float(g_umax[0]));
    float sw = 255.0f / (2.0f * __uint_as_float(g_umax[1]));

    if (blockIdx.x == 0) {
        __shared__ float s_mb;
        float m = 0.f;
        for (int i = threadIdx.x; i < DIM; i += blockDim.x) m = fmaxf(m, fabsf(b[i]));
        #pragma unroll
        for (int o = 16; o; o >>= 1) m = fmaxf(m, __shfl_xor_sync(0xFFFFFFFFu, m, o));
        __shared__ float sm[32];
        int w = threadIdx.x >> 5, l = threadIdx.x & 31;
        if (l == 0) sm[w] = m;
        __syncthreads();
        if (w == 0) {
            m = (l < (int)(blockDim.x >> 5)) ? sm[l] : 0.f;
            #pragma unroll
            for (int o = 16; o; o >>= 1) m = fmaxf(m, __shfl_xor_sync(0xFFFFFFFFu, m, o));
            if (l == 0) s_mb = m;
        }
        __syncthreads();
        float b_s = 255.0f / (2.0f * s_mb);
        float rb  = (sx * sw) / b_s;
        for (int i = threadIdx.x; i < DIM; i += blockDim.x) {
            float base = fminf(127.f, fmaxf(-128.f, rintf(b[i] * b_s)));
            g_bq[i] = rintf(base * rb);  // |val| << 2^31 -> accum-range clip is a no-op
        }
    }

    const int n16 = NELEM / 16;
    for (int i = blockIdx.x * blockDim.x + threadIdx.x; i < 2 * n16; i += gridDim.x * blockDim.x) {
        int which = i >= n16;
        int idx = which ? i - n16 : i;
        const float4* src = which ? W : x;
        float s = which ? sw : sx;
        int4* dst = reinterpret_cast<int4*>(which ? g_wq8 : g_xq8);
        int p[4];
        #pragma unroll
        for (int j = 0; j < 4; j++) {
            float4 v = src[idx * 4 + j];
            int q0 = max(-128, min(127, __float2int_rn(v.x * s)));
            int q1 = max(-128, min(127, __float2int_rn(v.y * s)));
            int q2 = max(-128, min(127, __float2int_rn(v.z * s)));
            int q3 = max(-128, min(127, __float2int_rn(v.w * s)));
            p[j] = (q0 & 0xFF) | ((q1 & 0xFF) << 8) | ((q2 & 0xFF) << 16) | ((q3 & 0xFF) << 24);
        }
        dst[idx] = make_int4(p[0], p[1], p[2], p[3]);
    }
}

__global__ void k_requant(float4* __restrict__ out, int n4) {
    float in_s   = 255.0f / (2.0f * __uint_as_float(g_umax[0]));
    float w_s    = 255.0f / (2.0f * __uint_as_float(g_umax[1]));
    float acc_s  = in_s * w_s;
    float out_sat = __uint_as_float(g_umax[3]) / acc_s;
    float out_s  = 255.0f / (2.0f * out_sat);
    float ratio  = out_s / acc_s;
    const float4* acc = reinterpret_cast<const float4*>(g_accum);
    for (int i = blockIdx.x * blockDim.x + threadIdx.x; i < n4; i += gridDim.x * blockDim.x) {
        float4 v = acc[i];
        float4 o;
        o.x = fminf(127.f, fmaxf(-128.f, rintf(v.x * ratio))) / out_s;
        o.y = fminf(127.f, fmaxf(-128.f, rintf(v.y * ratio))) / out_s;
        o.z = fminf(127.f, fmaxf(-128.f, rintf(v.z * ratio))) / out_s;
        o.w = fminf(127.f, fmaxf(-128.f, rintf(v.w * ratio))) / out_s;
        out[i] = o;
    }
}

// ============================================================================
// int8 GEMM: accum[m,n] = sum_k xq[m,k]*wq[n,k] + bq[n]; plus global max|accum|
//   block 128x128, BK=128, 256 threads / 8 warps (warp 64x32), 2 CTAs/SM,
//   3-stage cp.async pipeline, ldmatrix.x4, mma.sync.m16n8k32.s8.s8.s32
// ============================================================================
#define BM 128
#define BN 128
#define BK 128
#define NSTAGE 3
#define KSTAGES (DIM / BK)     // 32
#define ROWPAD 144             // 128B rows + 16: 8-row ldmatrix banks distinct, 16B aligned
#define A_STAGE_BYTES (BM * ROWPAD)                   // 18432
#define B_STAGE_BYTES (BN * ROWPAD)                   // 18432
#define GEMM_SMEM_BYTES (NSTAGE * (A_STAGE_BYTES + B_STAGE_BYTES))  // 110592
#define NTHREADS 256

__device__ __forceinline__ uint32_t smem_u32(const void* p) {
    uint32_t a;
    asm("{ .reg .u64 t; cvta.to.shared.u64 t, %1; cvt.u32.u64 %0, t; }" : "=r"(a) : "l"(p));
    return a;
}

__device__ __forceinline__ void cpasync16(uint32_t dst, const void* src) {
    asm volatile("cp.async.cg.shared.global [%0], [%1], 16;" :: "r"(dst), "l"(src) : "memory");
}
#define CP_COMMIT() asm volatile("cp.async.commit_group;" ::: "memory")
#define CP_WAIT1()  asm volatile("cp.async.wait_group 1;" ::: "memory")

__device__ __forceinline__ void ldsm4(unsigned& r0, unsigned& r1, unsigned& r2, unsigned& r3,
                                      uint32_t addr) {
    asm volatile("ldmatrix.sync.aligned.m8n8.x4.shared.b16 {%0,%1,%2,%3}, [%4];"
                 : "=r"(r0), "=r"(r1), "=r"(r2), "=r"(r3) : "r"(addr));
}

__device__ __forceinline__ void mma_s8(int* d, const unsigned* a, const unsigned* b) {
    asm volatile(
        "mma.sync.aligned.m16n8k32.row.col.s32.s8.s8.s32 "
        "{%0,%1,%2,%3}, {%4,%5,%6,%7}, {%8,%9}, {%0,%1,%2,%3};"
        : "+r"(d[0]), "+r"(d[1]), "+r"(d[2]), "+r"(d[3])
        : "r"(a[0]), "r"(a[1]), "r"(a[2]), "r"(a[3]), "r"(b[0]), "r"(b[1]));
}

__device__ __forceinline__ void load_stage(uint32_t sA, uint32_t sB, int s,
                                           const signed char* Ag, const signed char* Bg,
                                           int tid) {
    int k0 = s * BK;
    // A and B: 128 rows x 8 16B-chunks = 1024 chunks each; 256 threads x 4 iters
    #pragma unroll
    for (int i = 0; i < 4; i++) {
        int chunk = tid + i * NTHREADS;
        int r = chunk >> 3, c = chunk & 7;
        uint32_t soff = (uint32_t)(r * ROWPAD + c * 16);
        const signed char* gsrcA = Ag + (size_t)r * DIM + k0 + c * 16;
        const signed char* gsrcB = Bg + (size_t)r * DIM + k0 + c * 16;
        cpasync16(sA + soff, gsrcA);
        cpasync16(sB + soff, gsrcB);
    }
    CP_COMMIT();
}

__global__ void __launch_bounds__(NTHREADS, 2) k_gemm() {
    extern __shared__ char dsm[];
    __shared__ float s_bq[BN];

    const int tid  = threadIdx.x;
    const int wid  = tid >> 5;
    const int lane = tid & 31;
    const int m0 = blockIdx.y * BM;
    const int n0 = blockIdx.x * BN;
    const int warp_m = (wid >> 2) * 64;   // 0 or 64
    const int warp_n = (wid & 3) * 32;    // 0,32,64,96

    uint32_t sA0 = smem_u32(dsm);
    uint32_t sB0 = sA0 + NSTAGE * A_STAGE_BYTES;

    const signed char* Ag = g_xq8 + (size_t)m0 * DIM;
    const signed char* Bg = g_wq8 + (size_t)n0 * DIM;

    load_stage(sA0, sB0, 0, Ag, Bg, tid);
    load_stage(sA0 + A_STAGE_BYTES, sB0 + B_STAGE_BYTES, 1, Ag, Bg, tid);

    if (tid < BN) s_bq[tid] = g_bq[n0 + tid];

    int acc[4][4][4];
    #pragma unroll
    for (int im = 0; im < 4; im++)
        #pragma unroll
        for (int in = 0; in < 4; in++)
            #pragma unroll
            for (int j = 0; j < 4; j++) acc[im][in][j] = 0;

    // ldmatrix per-thread address components (mapping validated R3/R5/R7/R8)
    const uint32_t a_off = (uint32_t)((lane & 15) * ROWPAD + ((lane >> 4) << 4));
    const uint32_t b_off = (uint32_t)((((lane & 7) + ((lane >> 4) << 3)) * ROWPAD) + (((lane >> 3) & 1) << 4));

    for (int s = 0; s < KSTAGES; s++) {
        int buf = s % NSTAGE;
        CP_WAIT1();
        __syncthreads();

        // prefetch stage s+2 into buffer (s+2)%3 (its data was consumed at iter s-1)
        if (s + 2 < KSTAGES) {
            int nb = (s + 2) % NSTAGE;
            load_stage(sA0 + nb * A_STAGE_BYTES, sB0 + nb * B_STAGE_BYTES, s + 2, Ag, Bg, tid);
        } else {
            CP_COMMIT();
        }

        uint32_t aBase = sA0 + buf * A_STAGE_BYTES + (uint32_t)(warp_m * ROWPAD) + a_off;
        uint32_t bBase = sB0 + buf * B_STAGE_BYTES + (uint32_t)(warp_n * ROWPAD) + b_off;

        #pragma unroll
        for (int kstep = 0; kstep < 4; kstep++) {
            uint32_t kb = (uint32_t)(kstep * 32);
            unsigned afrag[4][4];
            #pragma unroll
            for (int im = 0; im < 4; im++)
                ldsm4(afrag[im][0], afrag[im][1], afrag[im][2], afrag[im][3],
                      aBase + (uint32_t)(im * 16 * ROWPAD) + kb);
            unsigned bfrag[4][2];
            #pragma unroll
            for (int p = 0; p < 2; p++)
                ldsm4(bfrag[2 * p][0], bfrag[2 * p][1], bfrag[2 * p + 1][0], bfrag[2 * p + 1][1],
                      bBase + (uint32_t)(p * 16 * ROWPAD) + kb);
            #pragma unroll
            for (int im = 0; im < 4; im++)
                #pragma unroll
                for (int in = 0; in < 4; in++)
                    mma_s8(acc[im][in], afrag[im], bfrag[in]);
        }
    }

    // -------- epilogue: + bq, write f32 accum, global max|accum| --------
    __syncthreads();
    const int r = lane >> 2;
    const int c = lane & 3;
    float lmax = 0.f;
    #pragma unroll
    for (int im = 0; im < 4; im++) {
        int r0 = m0 + warp_m + im * 16 + r;
        #pragma unroll
        for (int in = 0; in < 4; in++) {
            int cl = warp_n + in * 8 + c * 2;
            float b0 = s_bq[cl], b1 = s_bq[cl + 1];
            float v0 = (float)acc[im][in][0] + b0;
            float v1 = (float)acc[im][in][1] + b1;
            float v2 = (float)acc[im][in][2] + b0;
            float v3 = (float)acc[im][in][3] + b1;
            lmax = fmaxf(lmax, fmaxf(fmaxf(fabsf(v0), fabsf(v1)), fmaxf(fabsf(v2), fabsf(v3))));
            float2* p0 = reinterpret_cast<float2*>(g_accum + (size_t)r0 * DIM + n0 + cl);
            float2* p1 = reinterpret_cast<float2*>(g_accum + (size_t)(r0 + 8) * DIM + n0 + cl);
            *p0 = make_float2(v0, v1);
            *p1 = make_float2(v2, v3);
        }
    }
    #pragma unroll
    for (int o = 16; o; o >>= 1) lmax = fmaxf(lmax, __shfl_xor_sync(0xFFFFFFFFu, lmax, o));
    if (lane == 0) atomicMax(&g_umax[3], __float_as_uint(lmax));
}

// ============================================================================
// kernel_launch
// ============================================================================
extern "C" void kernel_launch(void* const* d_in, const int* in_sizes, int n_in,
                              void* d_out, int out_size) {
    const float* x = (const float*)d_in[0];
    const float* W = (const float*)d_in[1];
    const float* b = (const float*)d_in[2];

    cudaFuncSetAttribute(k_gemm, cudaFuncAttributeMaxDynamicSharedMemorySize, GEMM_SMEM_BYTES);

    k_init<<<1, 32>>>();
    k_maxabs2<<<2048, 256>>>((const float4*)x, (const float4*)W);
    k_quant8<<<2048, 256>>>((const float4*)x, (const float4*)W, b);

    dim3 grid(DIM / BN, DIM / BM);
    k_gemm<<<grid, NTHREADS, GEMM_SMEM_BYTES>>>();

    k_requant<<<2048, 256>>>((float4*)d_out, NELEM / 4);
}

// round 10
// speedup vs baseline: 1.2683x; 1.0192x over previous
#include <cuda_runtime.h>
#include <cstdint>

// ============================================================================
// Quantized linear layer (distiller RangeLinearQuantParamLayerWrapper)
//   x[4096,4096] f32, W[4096,4096] f32 ([out,in]), b[4096] f32 -> out[4096,4096] f32
//
// Target base sm_100 (no tcgen05). int8 mma.sync m16n8k32 s8*s8+s32 (exact).
// GEMM: block 128x128, 256 thr (8 warps, warp 64x32), BK=128, 3-stage cp.async,
// 2 CTAs/SM. R10: explicit double-buffered fragment pipeline (A streamed per-im,
// B double-buffered across ksteps) to hide ldsm->mma latency inside each warp.
// ============================================================================

#define DIM 4096
#define NELEM (DIM * DIM)

__device__ __align__(16) signed char g_xq8[NELEM];   // 16 MB
__device__ __align__(16) signed char g_wq8[NELEM];   // 16 MB
__device__ float         g_accum[NELEM];             // 64 MB
__device__ float         g_bq[DIM];
__device__ unsigned      g_umax[4];                  // max|x|,max|W|,(unused),max|accum|

// ============================================================================
// small kernels
// ============================================================================
__global__ void k_init() {
    if (threadIdx.x < 4) g_umax[threadIdx.x] = 0u;
}

__device__ __forceinline__ void maxabs_body(const float4* __restrict__ p, int n4,
                                            int slot, int bi, int nblk) {
    float m = 0.f;
    for (int i = bi * blockDim.x + threadIdx.x; i < n4; i += nblk * blockDim.x) {
        float4 v = p[i];
        m = fmaxf(m, fmaxf(fmaxf(fabsf(v.x), fabsf(v.y)), fmaxf(fabsf(v.z), fabsf(v.w))));
    }
    #pragma unroll
    for (int o = 16; o; o >>= 1) m = fmaxf(m, __shfl_xor_sync(0xFFFFFFFFu, m, o));
    __shared__ float sm[32];
    int w = threadIdx.x >> 5, l = threadIdx.x & 31;
    if (l == 0) sm[w] = m;
    __syncthreads();
    if (w == 0) {
        m = (l < (int)(blockDim.x >> 5)) ? sm[l] : 0.f;
        #pragma unroll
        for (int o = 16; o; o >>= 1) m = fmaxf(m, __shfl_xor_sync(0xFFFFFFFFu, m, o));
        if (l == 0) atomicMax(&g_umax[slot], __float_as_uint(m));
    }
}

__global__ void k_maxabs2(const float4* __restrict__ x, const float4* __restrict__ W) {
    int nb = gridDim.x >> 1;
    if ((int)blockIdx.x < nb) maxabs_body(x, NELEM / 4, 0, blockIdx.x, nb);
    else                      maxabs_body(W, NELEM / 4, 1, blockIdx.x - nb, nb);
}

// quantize x and W -> s8; block 0 additionally handles the bias path
__global__ void k_quant8(const float4* __restrict__ x, const float4* __restrict__ W,
                         const float* __restrict__ b) {
    float sx = 255.0f / (2.0f * __uint_as_float(g_umax[0]));
    float sw = 255.0f / (2.0f * __uint_as_float(g_umax[1]));

    if (blockIdx.x == 0) {
        __shared__ float s_mb;
        float m = 0.f;
        for (int i = threadIdx.x; i < DIM; i += blockDim.x) m = fmaxf(m, fabsf(b[i]));
        #pragma unroll
        for (int o = 16; o; o >>= 1) m = fmaxf(m, __shfl_xor_sync(0xFFFFFFFFu, m, o));
        __shared__ float sm[32];
        int w = threadIdx.x >> 5, l = threadIdx.x & 31;
        if (l == 0) sm[w] = m;
        __syncthreads();
        if (w == 0) {
            m = (l < (int)(blockDim.x >> 5)) ? sm[l] : 0.f;
            #pragma unroll
            for (int o = 16; o; o >>= 1) m = fmaxf(m, __shfl_xor_sync(0xFFFFFFFFu, m, o));
            if (l == 0) s_mb = m;
        }
        __syncthreads();
        float b_s = 255.0f / (2.0f * s_mb);
        float rb  = (sx * sw) / b_s;
        for (int i = threadIdx.x; i < DIM; i += blockDim.x) {
            float base = fminf(127.f, fmaxf(-128.f, rintf(b[i] * b_s)));
            g_bq[i] = rintf(base * rb);  // |val| << 2^31 -> accum-range clip is a no-op
        }
    }

    const int n16 = NELEM / 16;
    for (int i = blockIdx.x * blockDim.x + threadIdx.x; i < 2 * n16; i += gridDim.x * blockDim.x) {
        int which = i >= n16;
        int idx = which ? i - n16 : i;
        const float4* src = which ? W : x;
        float s = which ? sw : sx;
        int4* dst = reinterpret_cast<int4*>(which ? g_wq8 : g_xq8);
        int p[4];
        #pragma unroll
        for (int j = 0; j < 4; j++) {
            float4 v = src[idx * 4 + j];
            int q0 = max(-128, min(127, __float2int_rn(v.x * s)));
            int q1 = max(-128, min(127, __float2int_rn(v.y * s)));
            int q2 = max(-128, min(127, __float2int_rn(v.z * s)));
            int q3 = max(-128, min(127, __float2int_rn(v.w * s)));
            p[j] = (q0 & 0xFF) | ((q1 & 0xFF) << 8) | ((q2 & 0xFF) << 16) | ((q3 & 0xFF) << 24);
        }
        dst[idx] = make_int4(p[0], p[1], p[2], p[3]);
    }
}

__global__ void k_requant(float4* __restrict__ out, int n4) {
    float in_s   = 255.0f / (2.0f * __uint_as_float(g_umax[0]));
    float w_s    = 255.0f / (2.0f * __uint_as_float(g_umax[1]));
    float acc_s  = in_s * w_s;
    float out_sat = __uint_as_float(g_umax[3]) / acc_s;
    float out_s  = 255.0f / (2.0f * out_sat);
    float ratio  = out_s / acc_s;
    float inv_os = 1.0f / out_s;   // reciprocal once; per-element mul (<=2ulp vs div)
    const float4* acc = reinterpret_cast<const float4*>(g_accum);
    for (int i = blockIdx.x * blockDim.x + threadIdx.x; i < n4; i += gridDim.x * blockDim.x) {
        float4 v = acc[i];
        float4 o;
        o.x = fminf(127.f, fmaxf(-128.f, rintf(v.x * ratio))) * inv_os;
        o.y = fminf(127.f, fmaxf(-128.f, rintf(v.y * ratio))) * inv_os;
        o.z = fminf(127.f, fmaxf(-128.f, rintf(v.z * ratio))) * inv_os;
        o.w = fminf(127.f, fmaxf(-128.f, rintf(v.w * ratio))) * inv_os;
        out[i] = o;
    }
}

// ============================================================================
// int8 GEMM: accum[m,n] = sum_k xq[m,k]*wq[n,k] + bq[n]; plus global max|accum|
//   block 128x128, BK=128, 256 threads / 8 warps (warp 64x32), 2 CTAs/SM,
//   3-stage cp.async, ldmatrix.x4 with explicit double-buffered fragments
// ============================================================================
#define BM 128
#define BN 128
#define BK 128
#define NSTAGE 3
#define KSTAGES (DIM / BK)     // 32
#define ROWPAD 144
#define A_STAGE_BYTES (BM * ROWPAD)                   // 18432
#define B_STAGE_BYTES (BN * ROWPAD)                   // 18432
#define GEMM_SMEM_BYTES (NSTAGE * (A_STAGE_BYTES + B_STAGE_BYTES))  // 110592
#define NTHREADS 256

__device__ __forceinline__ uint32_t smem_u32(const void* p) {
    uint32_t a;
    asm("{ .reg .u64 t; cvta.to.shared.u64 t, %1; cvt.u32.u64 %0, t; }" : "=r"(a) : "l"(p));
    return a;
}

__device__ __forceinline__ void cpasync16(uint32_t dst, const void* src) {
    asm volatile("cp.async.cg.shared.global [%0], [%1], 16;" :: "r"(dst), "l"(src) : "memory");
}
#define CP_COMMIT() asm volatile("cp.async.commit_group;" ::: "memory")
#define CP_WAIT1()  asm volatile("cp.async.wait_group 1;" ::: "memory")

__device__ __forceinline__ void ldsm4(unsigned& r0, unsigned& r1, unsigned& r2, unsigned& r3,
                                      uint32_t addr) {
    asm volatile("ldmatrix.sync.aligned.m8n8.x4.shared.b16 {%0,%1,%2,%3}, [%4];"
                 : "=r"(r0), "=r"(r1), "=r"(r2), "=r"(r3) : "r"(addr));
}

__device__ __forceinline__ void mma_s8(int* d, const unsigned* a, const unsigned* b) {
    asm volatile(
        "mma.sync.aligned.m16n8k32.row.col.s32.s8.s8.s32 "
        "{%0,%1,%2,%3}, {%4,%5,%6,%7}, {%8,%9}, {%0,%1,%2,%3};"
        : "+r"(d[0]), "+r"(d[1]), "+r"(d[2]), "+r"(d[3])
        : "r"(a[0]), "r"(a[1]), "r"(a[2]), "r"(a[3]), "r"(b[0]), "r"(b[1]));
}

__device__ __forceinline__ void load_stage(uint32_t sA, uint32_t sB, int s,
                                           const signed char* Ag, const signed char* Bg,
                                           int tid) {
    int k0 = s * BK;
    #pragma unroll
    for (int i = 0; i < 4; i++) {
        int chunk = tid + i * NTHREADS;
        int r = chunk >> 3, c = chunk & 7;
        uint32_t soff = (uint32_t)(r * ROWPAD + c * 16);
        cpasync16(sA + soff, Ag + (size_t)r * DIM + k0 + c * 16);
        cpasync16(sB + soff, Bg + (size_t)r * DIM + k0 + c * 16);
    }
    CP_COMMIT();
}

__global__ void __launch_bounds__(NTHREADS, 2) k_gemm() {
    extern __shared__ char dsm[];
    __shared__ float s_bq[BN];

    const int tid  = threadIdx.x;
    const int wid  = tid >> 5;
    const int lane = tid & 31;
    const int m0 = blockIdx.y * BM;
    const int n0 = blockIdx.x * BN;
    const int warp_m = (wid >> 2) * 64;   // 0 or 64
    const int warp_n = (wid & 3) * 32;    // 0,32,64,96

    uint32_t sA0 = smem_u32(dsm);
    uint32_t sB0 = sA0 + NSTAGE * A_STAGE_BYTES;

    const signed char* Ag = g_xq8 + (size_t)m0 * DIM;
    const signed char* Bg = g_wq8 + (size_t)n0 * DIM;

    load_stage(sA0, sB0, 0, Ag, Bg, tid);
    load_stage(sA0 + A_STAGE_BYTES, sB0 + B_STAGE_BYTES, 1, Ag, Bg, tid);

    if (tid < BN) s_bq[tid] = g_bq[n0 + tid];

    int acc[4][4][4];
    #pragma unroll
    for (int im = 0; im < 4; im++)
        #pragma unroll
        for (int in = 0; in < 4; in++)
            #pragma unroll
            for (int j = 0; j < 4; j++) acc[im][in][j] = 0;

    // ldmatrix per-thread address components (mapping validated R3/R5/R7/R8/R9)
    const uint32_t a_off = (uint32_t)((lane & 15) * ROWPAD + ((lane >> 4) << 4));
    const uint32_t b_off = (uint32_t)((((lane & 7) + ((lane >> 4) << 3)) * ROWPAD) + (((lane >> 3) & 1) << 4));

    for (int s = 0; s < KSTAGES; s++) {
        int buf = s % NSTAGE;
        CP_WAIT1();
        __syncthreads();

        // prefetch stage s+2 into buffer (s+2)%3 (consumed at iter s-1)
        if (s + 2 < KSTAGES) {
            int nb = (s + 2) % NSTAGE;
            load_stage(sA0 + nb * A_STAGE_BYTES, sB0 + nb * B_STAGE_BYTES, s + 2, Ag, Bg, tid);
        } else {
            CP_COMMIT();
        }

        uint32_t aBase = sA0 + buf * A_STAGE_BYTES + (uint32_t)(warp_m * ROWPAD) + a_off;
        uint32_t bBase = sB0 + buf * B_STAGE_BYTES + (uint32_t)(warp_n * ROWPAD) + b_off;

        // ---- double-buffered fragment pipeline over 4 ksteps ----
        unsigned af[2][4];      // A: streamed per-im, ping-pong on im parity
        unsigned bf[2][4][2];   // B: ping-pong on kstep parity

        // prime: B frags for kstep 0, A frags for (kstep0, im0)
        ldsm4(bf[0][0][0], bf[0][0][1], bf[0][1][0], bf[0][1][1], bBase);
        ldsm4(bf[0][2][0], bf[0][2][1], bf[0][3][0], bf[0][3][1], bBase + (uint32_t)(16 * ROWPAD));
        ldsm4(af[0][0], af[0][1], af[0][2], af[0][3], aBase);

        #pragma unroll
        for (int k = 0; k < 4; k++) {
            const int cur = k & 1, nxt = cur ^ 1;
            const uint32_t kb_n = (uint32_t)((k + 1) * 32);
            #pragma unroll
            for (int im = 0; im < 4; im++) {
                const int ap = im & 1, an = ap ^ 1;     // note: 4k even -> im parity == global parity
                if (im < 3) {
                    // prefetch A for im+1 (this kstep)
                    ldsm4(af[an][0], af[an][1], af[an][2], af[an][3],
                          aBase + (uint32_t)((im + 1) * 16 * ROWPAD) + (uint32_t)(k * 32));
                } else if (k < 3) {
                    // prefetch B + A(im0) for next kstep
                    ldsm4(bf[nxt][0][0], bf[nxt][0][1], bf[nxt][1][0], bf[nxt][1][1], bBase + kb_n);
                    ldsm4(bf[nxt][2][0], bf[nxt][2][1], bf[nxt][3][0], bf[nxt][3][1],
                          bBase + (uint32_t)(16 * ROWPAD) + kb_n);
                    ldsm4(af[an][0], af[an][1], af[an][2], af[an][3], aBase + kb_n);
                }
                #pragma unroll
                for (int in = 0; in < 4; in++)
                    mma_s8(acc[im][in], af[ap], bf[cur][in]);
            }
        }
    }

    // -------- epilogue: + bq, write f32 accum, global max|accum| --------
    __syncthreads();
    const int r = lane >> 2;
    const int c = lane & 3;
    float lmax = 0.f;
    #pragma unroll
    for (int im = 0; im < 4; im++) {
        int r0 = m0 + warp_m + im * 16 + r;
        #pragma unroll
        for (int in = 0; in < 4; in++) {
            int cl = warp_n + in * 8 + c * 2;
            float b0 = s_bq[cl], b1 = s_bq[cl + 1];
            float v0 = (float)acc[im][in][0] + b0;
            float v1 = (float)acc[im][in][1] + b1;
            float v2 = (float)acc[im][in][2] + b0;
            float v3 = (float)acc[im][in][3] + b1;
            lmax = fmaxf(lmax, fmaxf(fmaxf(fabsf(v0), fabsf(v1)), fmaxf(fabsf(v2), fabsf(v3))));
            float2* p0 = reinterpret_cast<float2*>(g_accum + (size_t)r0 * DIM + n0 + cl);
            float2* p1 = reinterpret_cast<float2*>(g_accum + (size_t)(r0 + 8) * DIM + n0 + cl);
            *p0 = make_float2(v0, v1);
            *p1 = make_float2(v2, v3);
        }
    }
    #pragma unroll
    for (int o = 16; o; o >>= 1) lmax = fmaxf(lmax, __shfl_xor_sync(0xFFFFFFFFu, lmax, o));
    if (lane == 0) atomicMax(&g_umax[3], __float_as_uint(lmax));
}

// ============================================================================
// kernel_launch
// ============================================================================
extern "C" void kernel_launch(void* const* d_in, const int* in_sizes, int n_in,
                              void* d_out, int out_size) {
    const float* x = (const float*)d_in[0];
    const float* W = (const float*)d_in[1];
    const float* b = (const float*)d_in[2];

    cudaFuncSetAttribute(k_gemm, cudaFuncAttributeMaxDynamicSharedMemorySize, GEMM_SMEM_BYTES);

    k_init<<<1, 32>>>();
    k_maxabs2<<<2048, 256>>>((const float4*)x, (const float4*)W);
    k_quant8<<<2048, 256>>>((const float4*)x, (const float4*)W, b);

    dim3 grid(DIM / BN, DIM / BM);
    k_gemm<<<grid, NTHREADS, GEMM_SMEM_BYTES>>>();

    k_requant<<<2048, 256>>>((float4*)d_out, NELEM / 4);
}

// round 11
// speedup vs baseline: 1.2711x; 1.0022x over previous
#include <cuda_runtime.h>
#include <cstdint>

// ============================================================================
// Quantized linear layer (distiller RangeLinearQuantParamLayerWrapper)
//   x[4096,4096] f32, W[4096,4096] f32 ([out,in]), b[4096] f32 -> out[4096,4096] f32
//
// Target base sm_100 (no tcgen05). int8 mma.sync m16n8k32 s8*s8+s32 (exact).
// GEMM: PERSISTENT grid (296 CTAs = 2/SM) with atomic tile ticketing to kill
// tile-quantization tail; block 128x128, 8 warps (warp 64x32), BK=128,
// 3-stage cp.async, double-buffered ldmatrix fragments (R10-verified loop).
// ============================================================================

#define DIM 4096
#define NELEM (DIM * DIM)

__device__ __align__(16) signed char g_xq8[NELEM];   // 16 MB
__device__ __align__(16) signed char g_wq8[NELEM];   // 16 MB
__device__ float         g_accum[NELEM];             // 64 MB
__device__ float         g_bq[DIM];
__device__ unsigned      g_umax[4];                  // max|x|,max|W|,(unused),max|accum|
__device__ unsigned      g_ticket;                   // persistent-GEMM tile ticket

// ============================================================================
// small kernels
// ============================================================================
__global__ void k_init() {
    if (threadIdx.x < 4) g_umax[threadIdx.x] = 0u;
    if (threadIdx.x == 0) g_ticket = 0u;
}

__device__ __forceinline__ void maxabs_body(const float4* __restrict__ p, int n4,
                                            int slot, int bi, int nblk) {
    float m = 0.f;
    for (int i = bi * blockDim.x + threadIdx.x; i < n4; i += nblk * blockDim.x) {
        float4 v = p[i];
        m = fmaxf(m, fmaxf(fmaxf(fabsf(v.x), fabsf(v.y)), fmaxf(fabsf(v.z), fabsf(v.w))));
    }
    #pragma unroll
    for (int o = 16; o; o >>= 1) m = fmaxf(m, __shfl_xor_sync(0xFFFFFFFFu, m, o));
    __shared__ float sm[32];
    int w = threadIdx.x >> 5, l = threadIdx.x & 31;
    if (l == 0) sm[w] = m;
    __syncthreads();
    if (w == 0) {
        m = (l < (int)(blockDim.x >> 5)) ? sm[l] : 0.f;
        #pragma unroll
        for (int o = 16; o; o >>= 1) m = fmaxf(m, __shfl_xor_sync(0xFFFFFFFFu, m, o));
        if (l == 0) atomicMax(&g_umax[slot], __float_as_uint(m));
    }
}

__global__ void k_maxabs2(const float4* __restrict__ x, const float4* __restrict__ W) {
    int nb = gridDim.x >> 1;
    if ((int)blockIdx.x < nb) maxabs_body(x, NELEM / 4, 0, blockIdx.x, nb);
    else                      maxabs_body(W, NELEM / 4, 1, blockIdx.x - nb, nb);
}

// quantize x and W -> s8; block 0 additionally handles the bias path
__global__ void k_quant8(const float4* __restrict__ x, const float4* __restrict__ W,
                         const float* __restrict__ b) {
    float sx = 255.0f / (2.0f * __uint_as_float(g_umax[0]));
    float sw = 255.0f / (2.0f * __uint_as_float(g_umax[1]));

    if (blockIdx.x == 0) {
        __shared__ float s_mb;
        float m = 0.f;
        for (int i = threadIdx.x; i < DIM; i += blockDim.x) m = fmaxf(m, fabsf(b[i]));
        #pragma unroll
        for (int o = 16; o; o >>= 1) m = fmaxf(m, __shfl_xor_sync(0xFFFFFFFFu, m, o));
        __shared__ float sm[32];
        int w = threadIdx.x >> 5, l = threadIdx.x & 31;
        if (l == 0) sm[w] = m;
        __syncthreads();
        if (w == 0) {
            m = (l < (int)(blockDim.x >> 5)) ? sm[l] : 0.f;
            #pragma unroll
            for (int o = 16; o; o >>= 1) m = fmaxf(m, __shfl_xor_sync(0xFFFFFFFFu, m, o));
            if (l == 0) s_mb = m;
        }
        __syncthreads();
        float b_s = 255.0f / (2.0f * s_mb);
        float rb  = (sx * sw) / b_s;
        for (int i = threadIdx.x; i < DIM; i += blockDim.x) {
            float base = fminf(127.f, fmaxf(-128.f, rintf(b[i] * b_s)));
            g_bq[i] = rintf(base * rb);  // |val| << 2^31 -> accum-range clip is a no-op
        }
    }

    const int n16 = NELEM / 16;
    for (int i = blockIdx.x * blockDim.x + threadIdx.x; i < 2 * n16; i += gridDim.x * blockDim.x) {
        int which = i >= n16;
        int idx = which ? i - n16 : i;
        const float4* src = which ? W : x;
        float s = which ? sw : sx;
        int4* dst = reinterpret_cast<int4*>(which ? g_wq8 : g_xq8);
        int p[4];
        #pragma unroll
        for (int j = 0; j < 4; j++) {
            float4 v = src[idx * 4 + j];
            int q0 = max(-128, min(127, __float2int_rn(v.x * s)));
            int q1 = max(-128, min(127, __float2int_rn(v.y * s)));
            int q2 = max(-128, min(127, __float2int_rn(v.z * s)));
            int q3 = max(-128, min(127, __float2int_rn(v.w * s)));
            p[j] = (q0 & 0xFF) | ((q1 & 0xFF) << 8) | ((q2 & 0xFF) << 16) | ((q3 & 0xFF) << 24);
        }
        dst[idx] = make_int4(p[0], p[1], p[2], p[3]);
    }
}

__global__ void k_requant(float4* __restrict__ out, int n4) {
    float in_s   = 255.0f / (2.0f * __uint_as_float(g_umax[0]));
    float w_s    = 255.0f / (2.0f * __uint_as_float(g_umax[1]));
    float acc_s  = in_s * w_s;
    float out_sat = __uint_as_float(g_umax[3]) / acc_s;
    float out_s  = 255.0f / (2.0f * out_sat);
    float ratio  = out_s / acc_s;
    float inv_os = 1.0f / out_s;
    const float4* acc = reinterpret_cast<const float4*>(g_accum);
    for (int i = blockIdx.x * blockDim.x + threadIdx.x; i < n4; i += gridDim.x * blockDim.x) {
        float4 v = acc[i];
        float4 o;
        o.x = fminf(127.f, fmaxf(-128.f, rintf(v.x * ratio))) * inv_os;
        o.y = fminf(127.f, fmaxf(-128.f, rintf(v.y * ratio))) * inv_os;
        o.z = fminf(127.f, fmaxf(-128.f, rintf(v.z * ratio))) * inv_os;
        o.w = fminf(127.f, fmaxf(-128.f, rintf(v.w * ratio))) * inv_os;
        out[i] = o;
    }
}

// ============================================================================
// persistent int8 GEMM with atomic tile ticketing
//   tiles: 32x32 grid of 128x128; ticket t -> by = t>>5 (M), bx = t&31 (N)
// ============================================================================
#define BM 128
#define BN 128
#define BK 128
#define NSTAGE 3
#define KSTAGES (DIM / BK)     // 32
#define ROWPAD 144
#define A_STAGE_BYTES (BM * ROWPAD)                   // 18432
#define B_STAGE_BYTES (BN * ROWPAD)                   // 18432
#define GEMM_SMEM_BYTES (NSTAGE * (A_STAGE_BYTES + B_STAGE_BYTES))  // 110592
#define NTHREADS 256
#define NTILES 1024
#define GEMM_GRID 296          // 2 CTAs x 148 SMs

__device__ __forceinline__ uint32_t smem_u32(const void* p) {
    uint32_t a;
    asm("{ .reg .u64 t; cvta.to.shared.u64 t, %1; cvt.u32.u64 %0, t; }" : "=r"(a) : "l"(p));
    return a;
}

__device__ __forceinline__ void cpasync16(uint32_t dst, const void* src) {
    asm volatile("cp.async.cg.shared.global [%0], [%1], 16;" :: "r"(dst), "l"(src) : "memory");
}
#define CP_COMMIT() asm volatile("cp.async.commit_group;" ::: "memory")
#define CP_WAIT1()  asm volatile("cp.async.wait_group 1;" ::: "memory")

__device__ __forceinline__ void ldsm4(unsigned& r0, unsigned& r1, unsigned& r2, unsigned& r3,
                                      uint32_t addr) {
    asm volatile("ldmatrix.sync.aligned.m8n8.x4.shared.b16 {%0,%1,%2,%3}, [%4];"
                 : "=r"(r0), "=r"(r1), "=r"(r2), "=r"(r3) : "r"(addr));
}

__device__ __forceinline__ void mma_s8(int* d, const unsigned* a, const unsigned* b) {
    asm volatile(
        "mma.sync.aligned.m16n8k32.row.col.s32.s8.s8.s32 "
        "{%0,%1,%2,%3}, {%4,%5,%6,%7}, {%8,%9}, {%0,%1,%2,%3};"
        : "+r"(d[0]), "+r"(d[1]), "+r"(d[2]), "+r"(d[3])
        : "r"(a[0]), "r"(a[1]), "r"(a[2]), "r"(a[3]), "r"(b[0]), "r"(b[1]));
}

__device__ __forceinline__ void load_stage(uint32_t sA, uint32_t sB, int s,
                                           const signed char* Ag, const signed char* Bg,
                                           int tid) {
    int k0 = s * BK;
    #pragma unroll
    for (int i = 0; i < 4; i++) {
        int chunk = tid + i * NTHREADS;
        int r = chunk >> 3, c = chunk & 7;
        uint32_t soff = (uint32_t)(r * ROWPAD + c * 16);
        cpasync16(sA + soff, Ag + (size_t)r * DIM + k0 + c * 16);
        cpasync16(sB + soff, Bg + (size_t)r * DIM + k0 + c * 16);
    }
    CP_COMMIT();
}

__global__ void __launch_bounds__(NTHREADS, 2) k_gemm() {
    extern __shared__ char dsm[];
    __shared__ float s_bq[BN];
    __shared__ unsigned s_tile;

    const int tid  = threadIdx.x;
    const int wid  = tid >> 5;
    const int lane = tid & 31;
    const int warp_m = (wid >> 2) * 64;   // 0 or 64
    const int warp_n = (wid & 3) * 32;    // 0,32,64,96

    uint32_t sA0 = smem_u32(dsm);
    uint32_t sB0 = sA0 + NSTAGE * A_STAGE_BYTES;

    // ldmatrix per-thread address components (mapping validated R3/R5/R7-R10)
    const uint32_t a_off = (uint32_t)((lane & 15) * ROWPAD + ((lane >> 4) << 4));
    const uint32_t b_off = (uint32_t)((((lane & 7) + ((lane >> 4) << 3)) * ROWPAD) + (((lane >> 3) & 1) << 4));
    const int r = lane >> 2;
    const int c = lane & 3;

    for (;;) {
        if (tid == 0) s_tile = atomicAdd(&g_ticket, 1u);
        __syncthreads();                 // ticket visible; fences prior tile's smem reads
        const unsigned t = s_tile;
        if (t >= NTILES) break;

        const int m0 = (int)(t >> 5) * BM;
        const int n0 = (int)(t & 31) * BN;
        const signed char* Ag = g_xq8 + (size_t)m0 * DIM;
        const signed char* Bg = g_wq8 + (size_t)n0 * DIM;

        load_stage(sA0, sB0, 0, Ag, Bg, tid);
        load_stage(sA0 + A_STAGE_BYTES, sB0 + B_STAGE_BYTES, 1, Ag, Bg, tid);

        if (tid < BN) s_bq[tid] = g_bq[n0 + tid];

        int acc[4][4][4];
        #pragma unroll
        for (int im = 0; im < 4; im++)
            #pragma unroll
            for (int in = 0; in < 4; in++)
                #pragma unroll
                for (int j = 0; j < 4; j++) acc[im][in][j] = 0;

        for (int s = 0; s < KSTAGES; s++) {
            int buf = s % NSTAGE;
            CP_WAIT1();
            __syncthreads();

            if (s + 2 < KSTAGES) {
                int nb = (s + 2) % NSTAGE;
                load_stage(sA0 + nb * A_STAGE_BYTES, sB0 + nb * B_STAGE_BYTES, s + 2, Ag, Bg, tid);
            } else {
                CP_COMMIT();             // keep pending-group count uniform across tiles
            }

            uint32_t aBase = sA0 + buf * A_STAGE_BYTES + (uint32_t)(warp_m * ROWPAD) + a_off;
            uint32_t bBase = sB0 + buf * B_STAGE_BYTES + (uint32_t)(warp_n * ROWPAD) + b_off;

            // ---- double-buffered fragment pipeline over 4 ksteps (R10-verified) ----
            unsigned af[2][4];
            unsigned bf[2][4][2];

            ldsm4(bf[0][0][0], bf[0][0][1], bf[0][1][0], bf[0][1][1], bBase);
            ldsm4(bf[0][2][0], bf[0][2][1], bf[0][3][0], bf[0][3][1], bBase + (uint32_t)(16 * ROWPAD));
            ldsm4(af[0][0], af[0][1], af[0][2], af[0][3], aBase);

            #pragma unroll
            for (int k = 0; k < 4; k++) {
                const int cur = k & 1, nxt = cur ^ 1;
                const uint32_t kb_n = (uint32_t)((k + 1) * 32);
                #pragma unroll
                for (int im = 0; im < 4; im++) {
                    const int ap = im & 1, an = ap ^ 1;
                    if (im < 3) {
                        ldsm4(af[an][0], af[an][1], af[an][2], af[an][3],
                              aBase + (uint32_t)((im + 1) * 16 * ROWPAD) + (uint32_t)(k * 32));
                    } else if (k < 3) {
                        ldsm4(bf[nxt][0][0], bf[nxt][0][1], bf[nxt][1][0], bf[nxt][1][1], bBase + kb_n);
                        ldsm4(bf[nxt][2][0], bf[nxt][2][1], bf[nxt][3][0], bf[nxt][3][1],
                              bBase + (uint32_t)(16 * ROWPAD) + kb_n);
                        ldsm4(af[an][0], af[an][1], af[an][2], af[an][3], aBase + kb_n);
                    }
                    #pragma unroll
                    for (int in = 0; in < 4; in++)
                        mma_s8(acc[im][in], af[ap], bf[cur][in]);
                }
            }
        }

        // -------- epilogue: + bq, write f32 accum, global max|accum| --------
        float lmax = 0.f;
        #pragma unroll
        for (int im = 0; im < 4; im++) {
            int r0 = m0 + warp_m + im * 16 + r;
            #pragma unroll
            for (int in = 0; in < 4; in++) {
                int cl = warp_n + in * 8 + c * 2;
                float b0 = s_bq[cl], b1 = s_bq[cl + 1];
                float v0 = (float)acc[im][in][0] + b0;
                float v1 = (float)acc[im][in][1] + b1;
                float v2 = (float)acc[im][in][2] + b0;
                float v3 = (float)acc[im][in][3] + b1;
                lmax = fmaxf(lmax, fmaxf(fmaxf(fabsf(v0), fabsf(v1)), fmaxf(fabsf(v2), fabsf(v3))));
                float2* p0 = reinterpret_cast<float2*>(g_accum + (size_t)r0 * DIM + n0 + cl);
                float2* p1 = reinterpret_cast<float2*>(g_accum + (size_t)(r0 + 8) * DIM + n0 + cl);
                *p0 = make_float2(v0, v1);
                *p1 = make_float2(v2, v3);
            }
        }
        #pragma unroll
        for (int o = 16; o; o >>= 1) lmax = fmaxf(lmax, __shfl_xor_sync(0xFFFFFFFFu, lmax, o));
        if (lane == 0) atomicMax(&g_umax[3], __float_as_uint(lmax));
        // next iteration's ticket __syncthreads fences s_bq reads before overwrite
    }
}

// ============================================================================
// kernel_launch
// ============================================================================
extern "C" void kernel_launch(void* const* d_in, const int* in_sizes, int n_in,
                              void* d_out, int out_size) {
    const float* x = (const float*)d_in[0];
    const float* W = (const float*)d_in[1];
    const float* b = (const float*)d_in[2];

    cudaFuncSetAttribute(k_gemm, cudaFuncAttributeMaxDynamicSharedMemorySize, GEMM_SMEM_BYTES);

    k_init<<<1, 32>>>();
    k_maxabs2<<<2048, 256>>>((const float4*)x, (const float4*)W);
    k_quant8<<<2048, 256>>>((const float4*)x, (const float4*)W, b);

    k_gemm<<<GEMM_GRID, NTHREADS, GEMM_SMEM_BYTES>>>();

    k_requant<<<2048, 256>>>((float4*)d_out, NELEM / 4);
}